// round 9
// baseline (speedup 1.0000x reference)
#include <cuda_runtime.h>
#include <math.h>

// ---------------------------------------------------------------------------
// Problem constants
// ---------------------------------------------------------------------------
#define BETA      10.0
#define LTAU      1000
#define N_NODES   256
#define N_IWN     256
#define BATCH     16
#define N_POLES   16

#define STEP_D    (9.99 / 999.0)            // linspace(0, BETA-DTAU, LTAU) step
#define LOG2E_F   1.4426950408889634f
#define PI_D      3.141592653589793
#define ZETA3     1.2020569031595942
#define ZETA5     1.0369277551433699
#define PG_CLAMP  1.3e36f                   // ~2^120 magnitude clamp for pg*rho^j

// Gauss-Legendre tables, computed on HOST (deterministic double Newton) each
// call and passed BY VALUE as kernel parameters -> baked into the graph node.
struct GLTab {
    float phi[N_NODES];
    float wgt[N_NODES];
};

// Per-(b,pole) partial G_tau: 256 * 1000 floats = 1 MB (static).
__device__ float g_partial[BATCH * N_POLES * LTAU];
// Per-batch completion tickets (zero-init; finisher resets to 0 every call).
__device__ int   g_cnt[BATCH];

__device__ __forceinline__ float fexp2(float x) {
    float y;
    asm("ex2.approx.ftz.f32 %0, %1;" : "=f"(y) : "f"(x));
    return y;
}

// ---- packed f32x2 helpers (Blackwell FFMA2 path, PTX-only) ----------------
__device__ __forceinline__ unsigned long long pk2(float lo, float hi) {
    unsigned long long r;
    asm("mov.b64 %0, {%1, %2};" : "=l"(r) : "f"(lo), "f"(hi));
    return r;
}
__device__ __forceinline__ void unpk2(float& lo, float& hi, unsigned long long v) {
    asm("mov.b64 {%0, %1}, %2;" : "=f"(lo), "=f"(hi) : "l"(v));
}
__device__ __forceinline__ unsigned long long fma2(unsigned long long a,
                                                   unsigned long long b,
                                                   unsigned long long c) {
    unsigned long long d;
    asm("fma.rn.f32x2 %0, %1, %2, %3;" : "=l"(d) : "l"(a), "l"(b), "l"(c));
    return d;
}

// ---------------------------------------------------------------------------
// Fused kernel.  Block = (b, pole); 128 threads.
//
// Phase 1 (quad): thread t precomputes nodes 2t, 2t+1:
//   E0(n, tau0) = 2^( q2*tau0 + d2 ),  q2 = -omega*log2e,
//   d2 = BETA*min(omega,0)*log2e,
//   pg = 0.5*(a - b*phi) * w / (1 + exp(-BETA*|omega|))
//   pg_j = pg * rho^j  (rho = 2^(q2*dtau), per-step magnitude-clamped)
// so term(n, tau0 + j*dtau) = pg_j * E0 -> all 8 tau-accumulators share ONE
// exponential: inner body = 2 EX2 + 8 FFMA2 per packed node-pair.
// Threads 0..124 each cover 8 consecutive taus; partials -> g_partial.
//
// Phase 2 (finisher): threadfence + per-batch ticket; the 16th block for a
// batch sums its 16 pole chunks (fixed order -> deterministic), computes the
// Matsubara-tail G0, writes out[b][0], and resets the ticket counter.
//   Re(res/(z-i*nu)) = (a*eps - b*(gam+nu)) / (eps^2 + (gam+nu)^2)
//   Re(c1)/iwn correction is purely imaginary -> drops
//   corrections: +Re(c2)/nu^2 + Im(c3)/nu^3 - Re(c4)/nu^4 - Im(c5)/nu^5
// ---------------------------------------------------------------------------
__global__ void __launch_bounds__(128) fused_kernel(
    const GLTab tab,
    const float* __restrict__ pre, const float* __restrict__ pim,
    const float* __restrict__ rre, const float* __restrict__ rim,
    float* __restrict__ out)
{
    __shared__ float4             sh_qd[128];     // {q2_a,d2_a,q2_b,d2_b}
    __shared__ ulonglong2         sh_pg[128][4];  // pg_j packed, j pairs
    __shared__ int                s_ticket;
    __shared__ double             red[128];

    const int bp = blockIdx.x;          // b*16 + p
    const int b  = bp >> 4;
    const int t  = threadIdx.x;

    // ---- precompute: one packed node-pair per thread ----
    {
        float eps = pre[bp];
        float gam = -pim[bp];
        float a   = rre[bp];
        float br  = rim[bp];

        float q2v[2], d2v[2], pj[2][8];
        #pragma unroll
        for (int k = 0; k < 2; ++k) {
            const int n = 2 * t + k;
            float phi = tab.phi[n];
            float wq  = tab.wgt[n];
            float omega = fmaf(gam, phi, eps);
            float s     = fabsf(omega);
            float q2 = -omega * LOG2E_F;
            float d2 = 10.0f * fminf(omega, 0.0f) * LOG2E_F;
            float gfac = 1.0f / (1.0f + fexp2(-10.0f * LOG2E_F * s));
            float pg = 0.5f * fmaf(-br, phi, a) * wq * gfac;
            float rho = fexp2(fminf(q2 * (float)STEP_D, 80.0f));
            q2v[k] = q2;
            d2v[k] = d2;
            pj[k][0] = pg;
            #pragma unroll
            for (int j = 1; j < 8; ++j) {
                float v = pj[k][j - 1] * rho;
                // magnitude clamp avoids inf; whenever active, the matching
                // E0 has flushed (or the true term is <= ~4e-5) -> safe
                pj[k][j] = copysignf(fminf(fabsf(v), PG_CLAMP), v);
            }
        }
        sh_qd[t] = make_float4(q2v[0], d2v[0], q2v[1], d2v[1]);
        #pragma unroll
        for (int j = 0; j < 4; ++j)
            sh_pg[t][j] = make_ulonglong2(pk2(pj[0][2 * j],     pj[1][2 * j]),
                                          pk2(pj[0][2 * j + 1], pj[1][2 * j + 1]));
    }
    __syncthreads();

    // ---- main quadrature loop: 8 taus per thread, shared E0 ----
    if (t < 125) {
        const int l0 = 8 * t;
        const float tau0 = (float)((double)l0 * STEP_D);

        unsigned long long A0 = 0, A1 = 0, A2 = 0, A3 = 0,
                           A4 = 0, A5 = 0, A6 = 0, A7 = 0;
        #pragma unroll 4
        for (int p = 0; p < 128; ++p) {
            float4 qd = sh_qd[p];                 // broadcast LDS.128
            float e0 = fexp2(fmaf(qd.x, tau0, qd.y));
            float e1 = fexp2(fmaf(qd.z, tau0, qd.w));
            unsigned long long E = pk2(e0, e1);
            ulonglong2 p01 = sh_pg[p][0];
            ulonglong2 p23 = sh_pg[p][1];
            ulonglong2 p45 = sh_pg[p][2];
            ulonglong2 p67 = sh_pg[p][3];
            A0 = fma2(p01.x, E, A0);
            A1 = fma2(p01.y, E, A1);
            A2 = fma2(p23.x, E, A2);
            A3 = fma2(p23.y, E, A3);
            A4 = fma2(p45.x, E, A4);
            A5 = fma2(p45.y, E, A5);
            A6 = fma2(p67.x, E, A6);
            A7 = fma2(p67.y, E, A7);
        }

        float lo, hi, r0, r1, r2, r3, r4, r5, r6, r7;
        unpk2(lo, hi, A0); r0 = lo + hi;
        unpk2(lo, hi, A1); r1 = lo + hi;
        unpk2(lo, hi, A2); r2 = lo + hi;
        unpk2(lo, hi, A3); r3 = lo + hi;
        unpk2(lo, hi, A4); r4 = lo + hi;
        unpk2(lo, hi, A5); r5 = lo + hi;
        unpk2(lo, hi, A6); r6 = lo + hi;
        unpk2(lo, hi, A7); r7 = lo + hi;

        float4* dst = (float4*)&g_partial[(size_t)bp * LTAU];
        dst[2 * t]     = make_float4(r0, r1, r2, r3);
        dst[2 * t + 1] = make_float4(r4, r5, r6, r7);
    }

    // ---- ticket: release stores, claim a ticket for this batch ----
    __threadfence();                     // each thread orders its own stores
    __syncthreads();                     // ... before thread 0's atomic
    if (t == 0) {
        int tk = atomicAdd(&g_cnt[b], 1);
        s_ticket = tk;
        if (tk == 15) __threadfence();   // acquire side
    }
    __syncthreads();
    if (s_ticket != 15) return;

    // =====================  FINISHER (one block per batch)  ================
    // ---- reduce 16 pole chunks for every tau (fixed order: deterministic) -
    const float4* src = (const float4*)&g_partial[(size_t)b * N_POLES * LTAU];
    #pragma unroll
    for (int rr = 0; rr < 2; ++rr) {
        const int g = t + rr * 128;      // float4 group (4 taus)
        if (g < 250) {
            float4 s = make_float4(0.f, 0.f, 0.f, 0.f);
            #pragma unroll
            for (int p = 0; p < N_POLES; ++p) {
                float4 v = src[(size_t)p * 250 + g];
                s.x += v.x; s.y += v.y; s.z += v.z; s.w += v.w;
            }
            *(float4*)(out + (size_t)b * LTAU + 4 * g) = s;
        }
    }

    // ---- G0 (Matsubara tail): thread t handles frequencies t and t+128 ----
    const float nu1 = (2.0f * (float)t + 1.0f) * (float)(PI_D / 10.0);
    const float nu2_ = (2.0f * (float)(t + 128) + 1.0f) * (float)(PI_D / 10.0);
    float F1 = 0.f, F2 = 0.f, s1 = 0.f, s2 = 0.f, s3 = 0.f, s4 = 0.f, s5 = 0.f;

    #pragma unroll
    for (int p = 0; p < N_POLES; ++p) {
        float eps = pre[b * N_POLES + p];
        float gam = -pim[b * N_POLES + p];
        float a   = rre[b * N_POLES + p];
        float bb  = rim[b * N_POLES + p];

        float D1 = gam + nu1;
        F1 += (a * eps - bb * D1) / fmaf(eps, eps, D1 * D1);
        float D2 = gam + nu2_;
        F2 += (a * eps - bb * D2) / fmaf(eps, eps, D2 * D2);

        // c-chain: c1 = -res ; c_{k+1} = c_k * z, z = eps - i*gam
        float zr = eps, zi = -gam;
        float cr = -a, ci = -bb;
        s1 += cr;
        float r2 = cr * zr - ci * zi, i2 = cr * zi + ci * zr;  s2 += r2;
        float r3 = r2 * zr - i2 * zi, i3 = r2 * zi + i2 * zr;  s3 += i3;
        float r4 = r3 * zr - i3 * zi, i4 = r3 * zi + i3 * zr;  s4 += r4;
        float r5 = r4 * zr - i4 * zi, i5 = r4 * zi + i4 * zr;  s5 += i5;
    }
    {
        float n2 = nu1 * nu1, n3 = n2 * nu1;
        F1 += s2 / n2 + s3 / n3 - s4 / (n2 * n2) - s5 / (n2 * n3);
        float m2 = nu2_ * nu2_, m3 = m2 * nu2_;
        F2 += s2 / m2 + s3 / m3 - s4 / (m2 * m2) - s5 / (m2 * m3);
    }

    red[t] = (double)F1 + (double)F2;
    __syncthreads();
    for (int off = 64; off > 0; off >>= 1) {
        if (t < off) red[t] += red[t + off];
        __syncthreads();
    }

    if (t == 0) {
        const double C0 = -0.5;
        const double C1 = -BETA / 4.0;
        const double C2 = -7.0 * ZETA3 * BETA * BETA / (4.0 * PI_D * PI_D * PI_D);
        const double C3 = BETA * BETA * BETA / 48.0;
        const double C4 = 31.0 * ZETA5 * BETA * BETA * BETA * BETA /
                          (16.0 * PI_D * PI_D * PI_D * PI_D * PI_D);
        double G0 = C0 * (double)s1 + C1 * (double)s2 + C2 * (double)s3 +
                    C3 * (double)s4 + C4 * (double)s5 +
                    2.0 * red[0] / BETA;
        out[(size_t)b * LTAU] = (float)G0;   // overwrites l=0 (same thread
                                             // wrote it in the reduce: ordered)
        atomicExch(&g_cnt[b], 0);            // reset for next graph replay
    }
}

// ---------------------------------------------------------------------------
// Host: Gauss-Legendre nodes/weights (double Newton, fixed iteration count ->
// deterministic).  Runs at capture/correctness time only; values are baked
// into the graph as kernel parameters.  No device allocation, no stream ops.
// ---------------------------------------------------------------------------
static void host_leggauss(GLTab* tab)
{
    const int n = N_NODES;
    for (int i = 0; i < n; ++i) {
        double z = cos(PI_D * ((double)i + 0.75) / ((double)n + 0.5));
        double pp = 1.0;
        for (int it = 0; it < 6; ++it) {          // fixed count: deterministic
            double p1 = z, p2 = 1.0;
            for (int j = 1; j < n; ++j) {
                double p0 = ((2.0 * j + 1.0) * z * p1 - (double)j * p2)
                            / ((double)j + 1.0);
                p2 = p1; p1 = p0;
            }
            pp = (double)n * (z * p1 - p2) / (z * z - 1.0);
            z -= p1 / pp;
        }
        tab->phi[i] = (float)tan(1.5707963267948966 * z);
        tab->wgt[i] = (float)(2.0 / ((1.0 - z * z) * pp * pp));
    }
}

// ---------------------------------------------------------------------------
// Launch
// ---------------------------------------------------------------------------
extern "C" void kernel_launch(void* const* d_in, const int* in_sizes, int n_in,
                              void* d_out, int out_size)
{
    const float* pre = (const float*)d_in[0];  // poles_re    [16,16]
    const float* pim = (const float*)d_in[1];  // poles_im    [16,16]
    const float* rre = (const float*)d_in[2];  // residues_re [16,16]
    const float* rim = (const float*)d_in[3];  // residues_im [16,16]
    float* out = (float*)d_out;                // [16,1000] float32

    GLTab tab;                                 // recomputed every call (no caching)
    host_leggauss(&tab);

    fused_kernel<<<BATCH * N_POLES, 128>>>(tab, pre, pim, rre, rim, out);
}